// round 2
// baseline (speedup 1.0000x reference)
#include <cuda_runtime.h>
#include <cstdint>

#define DM   1024
#define BATCH 4
#define SEQ  2048
#define NH   16
#define HD   64
#define MTOT (BATCH*SEQ)   /* 8192 */
#define EPS  1e-5f
#define SROW 68            /* padded row (floats) for attention smem tiles */

// ---------------- scratch (device globals; no allocations allowed) ----------
__device__ float g_qn[MTOT*DM];
__device__ float g_kn[MTOT*DM];
__device__ float g_vn[MTOT*DM];
__device__ float g_qp[MTOT*DM];
__device__ float g_kp[MTOT*DM];
__device__ float g_vp[MTOT*DM];
__device__ float g_ao[MTOT*DM];
__device__ float g_y [MTOT*DM];
__device__ float g_gate[MTOT];

// ---------------- tf32 mma m16n8k8 helper -----------------------------------
__device__ __forceinline__ void mma_tf32(float c[4], const uint32_t a[4], const uint32_t b[2]) {
    asm volatile(
        "mma.sync.aligned.m16n8k8.row.col.f32.tf32.tf32.f32 "
        "{%0,%1,%2,%3}, {%4,%5,%6,%7}, {%8,%9}, {%0,%1,%2,%3};\n"
        : "+f"(c[0]), "+f"(c[1]), "+f"(c[2]), "+f"(c[3])
        : "r"(a[0]), "r"(a[1]), "r"(a[2]), "r"(a[3]), "r"(b[0]), "r"(b[1]));
}

// split x into hi (tf32-rounded) + lo (tf32 of residual): 3xTF32 precision trick
__device__ __forceinline__ void split_tf32(float x, uint32_t& hi, uint32_t& lo) {
    uint32_t h;
    asm("cvt.rna.tf32.f32 %0, %1;" : "=r"(h) : "f"(x));
    float r = x - __uint_as_float(h);
    uint32_t l;
    asm("cvt.rna.tf32.f32 %0, %1;" : "=r"(l) : "f"(r));
    hi = h; lo = l;
}

// ---------------- fused pre-LN for q/k/v + gate ------------------------------
// grid (MTOT, 3), block 256. y=0: query (ln_q, also gate), y=1: key, y=2: value (ln_kv)
__global__ __launch_bounds__(256) void ln3_kernel(
    const float* __restrict__ q, const float* __restrict__ k, const float* __restrict__ v,
    const float* __restrict__ gq, const float* __restrict__ bq,
    const float* __restrict__ gkv, const float* __restrict__ bkv,
    const float* __restrict__ Wg,
    float* __restrict__ oq, float* __restrict__ ok, float* __restrict__ ov,
    float* __restrict__ gate)
{
    const int row = blockIdx.x, src = blockIdx.y;
    const float* x  = src == 0 ? q  : (src == 1 ? k  : v);
    float*       out= src == 0 ? oq : (src == 1 ? ok : ov);
    const float* gg = src == 0 ? gq : gkv;
    const float* bb = src == 0 ? bq : bkv;
    const int tid = threadIdx.x, lane = tid & 31, warp = tid >> 5;

    float4 xv = ((const float4*)(x + (size_t)row*DM))[tid];
    float s  = xv.x + xv.y + xv.z + xv.w;
    float ss = xv.x*xv.x + xv.y*xv.y + xv.z*xv.z + xv.w*xv.w;

    __shared__ __align__(16) float red[16];
    #pragma unroll
    for (int off = 16; off; off >>= 1) {
        s  += __shfl_xor_sync(0xffffffffu, s,  off);
        ss += __shfl_xor_sync(0xffffffffu, ss, off);
    }
    if (lane == 0) { red[warp] = s; red[8 + warp] = ss; }
    __syncthreads();
    float st = 0.f, sst = 0.f;
    #pragma unroll
    for (int i = 0; i < 8; i++) { st += red[i]; sst += red[8 + i]; }
    float mu   = st * (1.f/DM);
    float var  = sst * (1.f/DM) - mu*mu;
    float rstd = rsqrtf(var + EPS);

    float4 gv = ((const float4*)gg)[tid];
    float4 bv = ((const float4*)bb)[tid];
    float4 yv;
    yv.x = (xv.x - mu)*rstd*gv.x + bv.x;
    yv.y = (xv.y - mu)*rstd*gv.y + bv.y;
    yv.z = (xv.z - mu)*rstd*gv.z + bv.z;
    yv.w = (xv.w - mu)*rstd*gv.w + bv.w;
    ((float4*)(out + (size_t)row*DM))[tid] = yv;

    if (src == 0) {  // gate = sigmoid(qn . Wg)
        float4 wv = ((const float4*)Wg)[tid];
        float gp = yv.x*wv.x + yv.y*wv.y + yv.z*wv.z + yv.w*wv.w;
        #pragma unroll
        for (int off = 16; off; off >>= 1) gp += __shfl_xor_sync(0xffffffffu, gp, off);
        __syncthreads();
        if (lane == 0) red[warp] = gp;
        __syncthreads();
        if (tid == 0) {
            float t = 0.f;
            #pragma unroll
            for (int i = 0; i < 8; i++) t += red[i];
            gate[row] = 1.f / (1.f + __expf(-t));
        }
    }
}

// ---------------- 3xTF32 GEMM: C[M,N] = A[M,K] @ W[K,N] + bias (xgate) ------
// M=8192, N=1024, K=1024. BM=128, BN=64, BK=32. 256 threads, 8 warps (4x2).
__global__ __launch_bounds__(256) void gemm_tf32(
    const float* __restrict__ A, const float* __restrict__ W,
    const float* __restrict__ bias, const float* __restrict__ gate,
    float* __restrict__ C)
{
    __shared__ __align__(16) float As[128][36];
    __shared__ __align__(16) float Bs[32][68];
    const int tid = threadIdx.x, lane = tid & 31, warp = tid >> 5;
    const int bm = blockIdx.y * 128, bn = blockIdx.x * 64;
    const int wm = (warp >> 1) * 32, wn = (warp & 1) * 32;

    float acc[2][4][4] = {};

    for (int k0 = 0; k0 < 1024; k0 += 32) {
        __syncthreads();
        #pragma unroll
        for (int i = 0; i < 4; i++) {               // A tile 128x32
            int idx = (tid + i*256) * 4;
            int m = idx >> 5, kk = idx & 31;
            float4 vA = *(const float4*)(A + (size_t)(bm + m)*1024 + k0 + kk);
            *(float4*)&As[m][kk] = vA;
        }
        #pragma unroll
        for (int i = 0; i < 2; i++) {               // W tile 32x64
            int idx = (tid + i*256) * 4;
            int kk = idx >> 6, n = idx & 63;
            float4 vB = *(const float4*)(W + (size_t)(k0 + kk)*1024 + bn + n);
            *(float4*)&Bs[kk][n] = vB;
        }
        __syncthreads();

        #pragma unroll
        for (int kc = 0; kc < 4; kc++) {
            uint32_t ah[2][4], al[2][4];
            #pragma unroll
            for (int mi = 0; mi < 2; mi++) {
                int r = wm + mi*16 + (lane >> 2);
                int c = kc*8 + (lane & 3);
                split_tf32(As[r  ][c  ], ah[mi][0], al[mi][0]);
                split_tf32(As[r+8][c  ], ah[mi][1], al[mi][1]);
                split_tf32(As[r  ][c+4], ah[mi][2], al[mi][2]);
                split_tf32(As[r+8][c+4], ah[mi][3], al[mi][3]);
            }
            #pragma unroll
            for (int ni = 0; ni < 4; ni++) {
                uint32_t bh[2], bl[2];
                int c = wn + ni*8 + (lane >> 2);
                int r = kc*8 + (lane & 3);
                split_tf32(Bs[r  ][c], bh[0], bl[0]);
                split_tf32(Bs[r+4][c], bh[1], bl[1]);
                mma_tf32(acc[0][ni], ah[0], bh);
                mma_tf32(acc[0][ni], al[0], bh);
                mma_tf32(acc[0][ni], ah[0], bl);
                mma_tf32(acc[1][ni], ah[1], bh);
                mma_tf32(acc[1][ni], al[1], bh);
                mma_tf32(acc[1][ni], ah[1], bl);
            }
        }
    }

    #pragma unroll
    for (int mi = 0; mi < 2; mi++) {
        #pragma unroll
        for (int ni = 0; ni < 4; ni++) {
            int r0 = bm + wm + mi*16 + (lane >> 2);
            int c0 = bn + wn + ni*8 + 2*(lane & 3);
            float bz0 = bias[c0], bz1 = bias[c0 + 1];
            float v0 = acc[mi][ni][0] + bz0;
            float v1 = acc[mi][ni][1] + bz1;
            float v2 = acc[mi][ni][2] + bz0;
            float v3 = acc[mi][ni][3] + bz1;
            if (gate) {
                float gA = gate[r0], gB = gate[r0 + 8];
                v0 *= gA; v1 *= gA; v2 *= gB; v3 *= gB;
            }
            C[(size_t)r0*1024 + c0]         = v0;
            C[(size_t)r0*1024 + c0 + 1]     = v1;
            C[(size_t)(r0+8)*1024 + c0]     = v2;
            C[(size_t)(r0+8)*1024 + c0 + 1] = v3;
        }
    }
}

// ---------------- flash attention (3xTF32 mma, online softmax) ---------------
// grid (SEQ/64, NH, BATCH), 128 threads (4 warps x 16 q-rows). Hd=64.
__global__ __launch_bounds__(128) void attn_kernel(
    const float* __restrict__ Q, const float* __restrict__ K,
    const float* __restrict__ V, float* __restrict__ O)
{
    extern __shared__ float sm[];
    float* Qs = sm;
    float* Ks = sm + 64*SROW;
    float* Vs = sm + 2*64*SROW;
    float* Ps = sm + 3*64*SROW;

    const int tid = threadIdx.x, lane = tid & 31, warp = tid >> 5;
    const int qt = blockIdx.x, h = blockIdx.y, b = blockIdx.z;

    const float* qbase = Q + ((size_t)(b*SEQ + qt*64)*DM + h*HD);
    const float* kbase = K + ((size_t)(b*SEQ)*DM + h*HD);
    const float* vbase = V + ((size_t)(b*SEQ)*DM + h*HD);

    #pragma unroll
    for (int i = 0; i < 8; i++) {       // Q tile 64x64
        int idx = (tid + i*128)*4;
        int r = idx >> 6, c = idx & 63;
        *(float4*)&Qs[r*SROW + c] = *(const float4*)(qbase + (size_t)r*DM + c);
    }
    __syncthreads();

    uint32_t qh[8][4], ql[8][4];
    {
        int r = warp*16 + (lane >> 2);
        #pragma unroll
        for (int kc = 0; kc < 8; kc++) {
            int c = kc*8 + (lane & 3);
            split_tf32(Qs[r*SROW + c],         qh[kc][0], ql[kc][0]);
            split_tf32(Qs[(r+8)*SROW + c],     qh[kc][1], ql[kc][1]);
            split_tf32(Qs[r*SROW + c + 4],     qh[kc][2], ql[kc][2]);
            split_tf32(Qs[(r+8)*SROW + c + 4], qh[kc][3], ql[kc][3]);
        }
    }

    float o[8][4] = {};
    float mrow[2] = {-1e30f, -1e30f};
    float lrow[2] = {0.f, 0.f};

    for (int t = 0; t < SEQ/64; t++) {
        __syncthreads();
        #pragma unroll
        for (int i = 0; i < 8; i++) {   // K,V tiles 64x64 each
            int idx = (tid + i*128)*4;
            int r = idx >> 6, c = idx & 63;
            *(float4*)&Ks[r*SROW + c] = *(const float4*)(kbase + (size_t)(t*64 + r)*DM + c);
            *(float4*)&Vs[r*SROW + c] = *(const float4*)(vbase + (size_t)(t*64 + r)*DM + c);
        }
        __syncthreads();

        float s[8][4] = {};
        #pragma unroll
        for (int kc = 0; kc < 8; kc++) {
            #pragma unroll
            for (int ni = 0; ni < 8; ni++) {
                uint32_t bh[2], bl[2];
                int kr = ni*8 + (lane >> 2);
                int cc = kc*8 + (lane & 3);
                split_tf32(Ks[kr*SROW + cc],     bh[0], bl[0]);
                split_tf32(Ks[kr*SROW + cc + 4], bh[1], bl[1]);
                mma_tf32(s[ni], qh[kc], bh);
                mma_tf32(s[ni], ql[kc], bh);
                mma_tf32(s[ni], qh[kc], bl);
            }
        }
        #pragma unroll
        for (int ni = 0; ni < 8; ni++) {
            s[ni][0] *= 0.125f; s[ni][1] *= 0.125f;
            s[ni][2] *= 0.125f; s[ni][3] *= 0.125f;
        }

        // online softmax per row-half
        #pragma unroll
        for (int rh = 0; rh < 2; rh++) {
            float mx = -1e30f;
            #pragma unroll
            for (int ni = 0; ni < 8; ni++)
                mx = fmaxf(mx, fmaxf(s[ni][rh*2], s[ni][rh*2+1]));
            mx = fmaxf(mx, __shfl_xor_sync(0xffffffffu, mx, 1));
            mx = fmaxf(mx, __shfl_xor_sync(0xffffffffu, mx, 2));
            float mnew  = fmaxf(mrow[rh], mx);
            float alpha = __expf(mrow[rh] - mnew);
            mrow[rh] = mnew;
            float sum = 0.f;
            #pragma unroll
            for (int ni = 0; ni < 8; ni++) {
                s[ni][rh*2]   = __expf(s[ni][rh*2]   - mnew);
                s[ni][rh*2+1] = __expf(s[ni][rh*2+1] - mnew);
                sum += s[ni][rh*2] + s[ni][rh*2+1];
            }
            sum += __shfl_xor_sync(0xffffffffu, sum, 1);
            sum += __shfl_xor_sync(0xffffffffu, sum, 2);
            lrow[rh] = lrow[rh]*alpha + sum;
            #pragma unroll
            for (int ni = 0; ni < 8; ni++) { o[ni][rh*2] *= alpha; o[ni][rh*2+1] *= alpha; }
        }

        // P -> shared (per-warp rows, warp-private)
        {
            int r = warp*16 + (lane >> 2);
            #pragma unroll
            for (int ni = 0; ni < 8; ni++) {
                int c = ni*8 + 2*(lane & 3);
                Ps[r*SROW + c]         = s[ni][0];
                Ps[r*SROW + c + 1]     = s[ni][1];
                Ps[(r+8)*SROW + c]     = s[ni][2];
                Ps[(r+8)*SROW + c + 1] = s[ni][3];
            }
        }
        __syncwarp();

        // O += P @ V  (3xTF32)
        #pragma unroll
        for (int kc = 0; kc < 8; kc++) {
            uint32_t ph[4], pl[4];
            int r = warp*16 + (lane >> 2);
            int c = kc*8 + (lane & 3);
            split_tf32(Ps[r*SROW + c],         ph[0], pl[0]);
            split_tf32(Ps[(r+8)*SROW + c],     ph[1], pl[1]);
            split_tf32(Ps[r*SROW + c + 4],     ph[2], pl[2]);
            split_tf32(Ps[(r+8)*SROW + c + 4], ph[3], pl[3]);
            #pragma unroll
            for (int ni = 0; ni < 8; ni++) {
                uint32_t vh[2], vl[2];
                int kr = kc*8 + (lane & 3);
                int cc = ni*8 + (lane >> 2);
                split_tf32(Vs[kr*SROW + cc],     vh[0], vl[0]);
                split_tf32(Vs[(kr+4)*SROW + cc], vh[1], vl[1]);
                mma_tf32(o[ni], ph, vh);
                mma_tf32(o[ni], pl, vh);
                mma_tf32(o[ni], ph, vl);
            }
        }
        __syncwarp();
    }

    float inv0 = 1.f / lrow[0], inv1 = 1.f / lrow[1];
    int r = warp*16 + (lane >> 2);
    float* obase = O + ((size_t)(b*SEQ + qt*64)*DM + h*HD);
    #pragma unroll
    for (int ni = 0; ni < 8; ni++) {
        int c = ni*8 + 2*(lane & 3);
        obase[(size_t)r*DM + c]         = o[ni][0]*inv0;
        obase[(size_t)r*DM + c + 1]     = o[ni][1]*inv0;
        obase[(size_t)(r+8)*DM + c]     = o[ni][2]*inv1;
        obase[(size_t)(r+8)*DM + c + 1] = o[ni][3]*inv1;
    }
}

// ---------------- final LN ---------------------------------------------------
__global__ __launch_bounds__(256) void ln_out_kernel(
    const float* __restrict__ x, const float* __restrict__ gg,
    const float* __restrict__ bb, float* __restrict__ out)
{
    const int row = blockIdx.x;
    const int tid = threadIdx.x, lane = tid & 31, warp = tid >> 5;
    float4 xv = ((const float4*)(x + (size_t)row*DM))[tid];
    float s  = xv.x + xv.y + xv.z + xv.w;
    float ss = xv.x*xv.x + xv.y*xv.y + xv.z*xv.z + xv.w*xv.w;
    __shared__ __align__(16) float red[16];
    #pragma unroll
    for (int off = 16; off; off >>= 1) {
        s  += __shfl_xor_sync(0xffffffffu, s,  off);
        ss += __shfl_xor_sync(0xffffffffu, ss, off);
    }
    if (lane == 0) { red[warp] = s; red[8 + warp] = ss; }
    __syncthreads();
    float st = 0.f, sst = 0.f;
    #pragma unroll
    for (int i = 0; i < 8; i++) { st += red[i]; sst += red[8 + i]; }
    float mu   = st * (1.f/DM);
    float var  = sst * (1.f/DM) - mu*mu;
    float rstd = rsqrtf(var + EPS);
    float4 gv = ((const float4*)gg)[tid];
    float4 bv = ((const float4*)bb)[tid];
    float4 yv;
    yv.x = (xv.x - mu)*rstd*gv.x + bv.x;
    yv.y = (xv.y - mu)*rstd*gv.y + bv.y;
    yv.z = (xv.z - mu)*rstd*gv.z + bv.z;
    yv.w = (xv.w - mu)*rstd*gv.w + bv.w;
    ((float4*)(out + (size_t)row*DM))[tid] = yv;
}

// ---------------- launch -----------------------------------------------------
extern "C" void kernel_launch(void* const* d_in, const int* in_sizes, int n_in,
                              void* d_out, int out_size) {
    const float* query  = (const float*)d_in[0];
    const float* key_   = (const float*)d_in[1];
    const float* value  = (const float*)d_in[2];
    const float* Wq     = (const float*)d_in[3];
    const float* bq     = (const float*)d_in[4];
    const float* Wk     = (const float*)d_in[5];
    const float* bk     = (const float*)d_in[6];
    const float* Wv     = (const float*)d_in[7];
    const float* bv     = (const float*)d_in[8];
    const float* Wo     = (const float*)d_in[9];
    const float* bo     = (const float*)d_in[10];
    const float* Wg     = (const float*)d_in[11];
    const float* ln_q_g = (const float*)d_in[12];
    const float* ln_q_b = (const float*)d_in[13];
    const float* ln_kv_g= (const float*)d_in[14];
    const float* ln_kv_b= (const float*)d_in[15];
    const float* ln_o_g = (const float*)d_in[16];
    const float* ln_o_b = (const float*)d_in[17];

    float *qn, *kn, *vn, *qp, *kp, *vp, *ao, *y, *gate;
    cudaGetSymbolAddress((void**)&qn,  g_qn);
    cudaGetSymbolAddress((void**)&kn,  g_kn);
    cudaGetSymbolAddress((void**)&vn,  g_vn);
    cudaGetSymbolAddress((void**)&qp,  g_qp);
    cudaGetSymbolAddress((void**)&kp,  g_kp);
    cudaGetSymbolAddress((void**)&vp,  g_vp);
    cudaGetSymbolAddress((void**)&ao,  g_ao);
    cudaGetSymbolAddress((void**)&y,   g_y);
    cudaGetSymbolAddress((void**)&gate,g_gate);

    const int attn_smem = 4 * 64 * SROW * (int)sizeof(float);
    cudaFuncSetAttribute(attn_kernel, cudaFuncAttributeMaxDynamicSharedMemorySize, attn_smem);

    ln3_kernel<<<dim3(MTOT, 3), 256>>>(query, key_, value,
                                       ln_q_g, ln_q_b, ln_kv_g, ln_kv_b,
                                       Wg, qn, kn, vn, gate);
    gemm_tf32<<<dim3(16, 64), 256>>>(qn, Wq, bq, nullptr, qp);
    gemm_tf32<<<dim3(16, 64), 256>>>(kn, Wk, bk, nullptr, kp);
    gemm_tf32<<<dim3(16, 64), 256>>>(vn, Wv, bv, nullptr, vp);
    attn_kernel<<<dim3(SEQ/64, NH, BATCH), 128, attn_smem>>>(qp, kp, vp, ao);
    gemm_tf32<<<dim3(16, 64), 256>>>(ao, Wo, bo, gate, y);
    ln_out_kernel<<<MTOT, 256>>>(y, ln_o_g, ln_o_b, (float*)d_out);
}

// round 3
// speedup vs baseline: 1.0856x; 1.0856x over previous
#include <cuda_runtime.h>
#include <cstdint>

#define DM   1024
#define BATCH 4
#define SEQ  2048
#define NH   16
#define HD   64
#define MTOT (BATCH*SEQ)   /* 8192 */
#define EPS  1e-5f

// ---------------- scratch (device globals; no allocations allowed) ----------
__device__ float g_qn[MTOT*DM];
__device__ float g_kn[MTOT*DM];
__device__ float g_vn[MTOT*DM];
__device__ float g_qp[MTOT*DM];
__device__ float g_kp[MTOT*DM];
__device__ float g_vp[MTOT*DM];
__device__ float g_ao[MTOT*DM];
__device__ float g_y [MTOT*DM];
__device__ float g_gate[MTOT];

// ---------------- tf32 mma m16n8k8 helper -----------------------------------
__device__ __forceinline__ void mma_tf32(float c[4], const uint32_t a[4], const uint32_t b[2]) {
    asm volatile(
        "mma.sync.aligned.m16n8k8.row.col.f32.tf32.tf32.f32 "
        "{%0,%1,%2,%3}, {%4,%5,%6,%7}, {%8,%9}, {%0,%1,%2,%3};\n"
        : "+f"(c[0]), "+f"(c[1]), "+f"(c[2]), "+f"(c[3])
        : "r"(a[0]), "r"(a[1]), "r"(a[2]), "r"(a[3]), "r"(b[0]), "r"(b[1]));
}

// split x into hi (tf32-rounded) + lo (tf32 of residual): 3xTF32 precision trick
__device__ __forceinline__ void split_tf32(float x, uint32_t& hi, uint32_t& lo) {
    uint32_t h;
    asm("cvt.rna.tf32.f32 %0, %1;" : "=r"(h) : "f"(x));
    float r = x - __uint_as_float(h);
    uint32_t l;
    asm("cvt.rna.tf32.f32 %0, %1;" : "=r"(l) : "f"(r));
    hi = h; lo = l;
}

__device__ __forceinline__ void split4(float4 v, float4& h, float4& l) {
    uint32_t hh, ll;
    split_tf32(v.x, hh, ll); h.x = __uint_as_float(hh); l.x = __uint_as_float(ll);
    split_tf32(v.y, hh, ll); h.y = __uint_as_float(hh); l.y = __uint_as_float(ll);
    split_tf32(v.z, hh, ll); h.z = __uint_as_float(hh); l.z = __uint_as_float(ll);
    split_tf32(v.w, hh, ll); h.w = __uint_as_float(hh); l.w = __uint_as_float(ll);
}

// ---------------- fused pre-LN for q/k/v + gate ------------------------------
__global__ __launch_bounds__(256) void ln3_kernel(
    const float* __restrict__ q, const float* __restrict__ k, const float* __restrict__ v,
    const float* __restrict__ gq, const float* __restrict__ bq,
    const float* __restrict__ gkv, const float* __restrict__ bkv,
    const float* __restrict__ Wg,
    float* __restrict__ oq, float* __restrict__ ok, float* __restrict__ ov,
    float* __restrict__ gate)
{
    const int row = blockIdx.x, src = blockIdx.y;
    const float* x  = src == 0 ? q  : (src == 1 ? k  : v);
    float*       out= src == 0 ? oq : (src == 1 ? ok : ov);
    const float* gg = src == 0 ? gq : gkv;
    const float* bb = src == 0 ? bq : bkv;
    const int tid = threadIdx.x, lane = tid & 31, warp = tid >> 5;

    float4 xv = ((const float4*)(x + (size_t)row*DM))[tid];
    float s  = xv.x + xv.y + xv.z + xv.w;
    float ss = xv.x*xv.x + xv.y*xv.y + xv.z*xv.z + xv.w*xv.w;

    __shared__ __align__(16) float red[16];
    #pragma unroll
    for (int off = 16; off; off >>= 1) {
        s  += __shfl_xor_sync(0xffffffffu, s,  off);
        ss += __shfl_xor_sync(0xffffffffu, ss, off);
    }
    if (lane == 0) { red[warp] = s; red[8 + warp] = ss; }
    __syncthreads();
    float st = 0.f, sst = 0.f;
    #pragma unroll
    for (int i = 0; i < 8; i++) { st += red[i]; sst += red[8 + i]; }
    float mu   = st * (1.f/DM);
    float var  = sst * (1.f/DM) - mu*mu;
    float rstd = rsqrtf(var + EPS);

    float4 gv = ((const float4*)gg)[tid];
    float4 bv = ((const float4*)bb)[tid];
    float4 yv;
    yv.x = (xv.x - mu)*rstd*gv.x + bv.x;
    yv.y = (xv.y - mu)*rstd*gv.y + bv.y;
    yv.z = (xv.z - mu)*rstd*gv.z + bv.z;
    yv.w = (xv.w - mu)*rstd*gv.w + bv.w;
    ((float4*)(out + (size_t)row*DM))[tid] = yv;

    if (src == 0) {  // gate = sigmoid(qn . Wg)
        float4 wv = ((const float4*)Wg)[tid];
        float gp = yv.x*wv.x + yv.y*wv.y + yv.z*wv.z + yv.w*wv.w;
        #pragma unroll
        for (int off = 16; off; off >>= 1) gp += __shfl_xor_sync(0xffffffffu, gp, off);
        __syncthreads();
        if (lane == 0) red[warp] = gp;
        __syncthreads();
        if (tid == 0) {
            float t = 0.f;
            #pragma unroll
            for (int i = 0; i < 8; i++) t += red[i];
            gate[row] = 1.f / (1.f + __expf(-t));
        }
    }
}

// ---------------- 3xTF32 GEMM: C[M,N] = A[M,K] @ W[K,N] + bias (xgate) ------
// M=8192, N=1024, K=1024. BM=128, BN=128, BK=32. 256 threads, 8 warps (4x2).
// hi/lo splits done ONCE at smem-fill; register-prefetch double buffering.
#define ASTRIDE 36
#define BSTRIDE 132
__global__ __launch_bounds__(256) void gemm_tf32(
    const float* __restrict__ A, const float* __restrict__ W,
    const float* __restrict__ bias, const float* __restrict__ gate,
    float* __restrict__ C)
{
    extern __shared__ float gs[];
    float* Ah = gs;                       // 128*36
    float* Al = Ah + 128*ASTRIDE;
    float* Bh = Al + 128*ASTRIDE;         // 32*132
    float* Bl = Bh + 32*BSTRIDE;

    const int tid = threadIdx.x, lane = tid & 31, warp = tid >> 5;
    const int bm = blockIdx.y * 128, bn = blockIdx.x * 128;
    const int wm = (warp >> 1) * 32, wn = (warp & 1) * 64;

    float acc[2][8][4] = {};
    float4 pa[4], pb[4];

    auto loadT = [&](int k0) {
        #pragma unroll
        for (int i = 0; i < 4; i++) {
            int idx = (tid + i*256) * 4;
            int m = idx >> 5, kk = idx & 31;
            pa[i] = *(const float4*)(A + (size_t)(bm + m)*1024 + k0 + kk);
        }
        #pragma unroll
        for (int i = 0; i < 4; i++) {
            int idx = (tid + i*256) * 4;
            int kk = idx >> 7, n = idx & 127;
            pb[i] = *(const float4*)(W + (size_t)(k0 + kk)*1024 + bn + n);
        }
    };
    auto storeT = [&]() {
        #pragma unroll
        for (int i = 0; i < 4; i++) {
            int idx = (tid + i*256) * 4;
            int m = idx >> 5, kk = idx & 31;
            float4 h, l; split4(pa[i], h, l);
            *(float4*)&Ah[m*ASTRIDE + kk] = h;
            *(float4*)&Al[m*ASTRIDE + kk] = l;
        }
        #pragma unroll
        for (int i = 0; i < 4; i++) {
            int idx = (tid + i*256) * 4;
            int kk = idx >> 7, n = idx & 127;
            float4 h, l; split4(pb[i], h, l);
            *(float4*)&Bh[kk*BSTRIDE + n] = h;
            *(float4*)&Bl[kk*BSTRIDE + n] = l;
        }
    };

    loadT(0);
    storeT();
    __syncthreads();

    for (int k0 = 0; k0 < 1024; k0 += 32) {
        bool more = (k0 + 32 < 1024);
        if (more) loadT(k0 + 32);

        #pragma unroll
        for (int kc = 0; kc < 4; kc++) {
            uint32_t ah[2][4], al[2][4];
            #pragma unroll
            for (int mi = 0; mi < 2; mi++) {
                int r = wm + mi*16 + (lane >> 2);
                int c = kc*8 + (lane & 3);
                ah[mi][0] = __float_as_uint(Ah[r*ASTRIDE + c]);
                ah[mi][1] = __float_as_uint(Ah[(r+8)*ASTRIDE + c]);
                ah[mi][2] = __float_as_uint(Ah[r*ASTRIDE + c + 4]);
                ah[mi][3] = __float_as_uint(Ah[(r+8)*ASTRIDE + c + 4]);
                al[mi][0] = __float_as_uint(Al[r*ASTRIDE + c]);
                al[mi][1] = __float_as_uint(Al[(r+8)*ASTRIDE + c]);
                al[mi][2] = __float_as_uint(Al[r*ASTRIDE + c + 4]);
                al[mi][3] = __float_as_uint(Al[(r+8)*ASTRIDE + c + 4]);
            }
            #pragma unroll
            for (int ni = 0; ni < 8; ni++) {
                uint32_t bh[2], bl[2];
                int c = wn + ni*8 + (lane >> 2);
                int r = kc*8 + (lane & 3);
                bh[0] = __float_as_uint(Bh[r*BSTRIDE + c]);
                bh[1] = __float_as_uint(Bh[(r+4)*BSTRIDE + c]);
                bl[0] = __float_as_uint(Bl[r*BSTRIDE + c]);
                bl[1] = __float_as_uint(Bl[(r+4)*BSTRIDE + c]);
                #pragma unroll
                for (int mi = 0; mi < 2; mi++) {
                    mma_tf32(acc[mi][ni], ah[mi], bh);
                    mma_tf32(acc[mi][ni], al[mi], bh);
                    mma_tf32(acc[mi][ni], ah[mi], bl);
                }
            }
        }

        if (more) {
            __syncthreads();
            storeT();
            __syncthreads();
        }
    }

    #pragma unroll
    for (int mi = 0; mi < 2; mi++) {
        #pragma unroll
        for (int ni = 0; ni < 8; ni++) {
            int r0 = bm + wm + mi*16 + (lane >> 2);
            int c0 = bn + wn + ni*8 + 2*(lane & 3);
            float bz0 = bias[c0], bz1 = bias[c0 + 1];
            float v0 = acc[mi][ni][0] + bz0;
            float v1 = acc[mi][ni][1] + bz1;
            float v2 = acc[mi][ni][2] + bz0;
            float v3 = acc[mi][ni][3] + bz1;
            if (gate) {
                float gA = gate[r0], gB = gate[r0 + 8];
                v0 *= gA; v1 *= gA; v2 *= gB; v3 *= gB;
            }
            C[(size_t)r0*1024 + c0]         = v0;
            C[(size_t)r0*1024 + c0 + 1]     = v1;
            C[(size_t)(r0+8)*1024 + c0]     = v2;
            C[(size_t)(r0+8)*1024 + c0 + 1] = v3;
        }
    }
}

// ---------------- flash attention (3xTF32 mma, online softmax) ---------------
// grid (SEQ/128, NH, BATCH), 256 threads (8 warps x 16 q-rows). Hd=64.
// K/V tiles split hi/lo at fill time; P split per-warp at use (no redundancy).
#define KSTRIDE 68
#define PSTRIDE 68
__global__ __launch_bounds__(256) void attn_kernel(
    const float* __restrict__ Q, const float* __restrict__ K,
    const float* __restrict__ V, float* __restrict__ O)
{
    extern __shared__ float sm[];
    float* Kh = sm;                         // 64*68
    float* Kl = Kh + 64*KSTRIDE;
    float* Vh = Kl + 64*KSTRIDE;
    float* Vl = Vh + 64*KSTRIDE;
    float* Ps = Vl + 64*KSTRIDE;            // 128*68 (also Q staging)

    const int tid = threadIdx.x, lane = tid & 31, warp = tid >> 5;
    const int qt = blockIdx.x, h = blockIdx.y, b = blockIdx.z;

    const float* qbase = Q + ((size_t)(b*SEQ + qt*128)*DM + h*HD);
    const float* kbase = K + ((size_t)(b*SEQ)*DM + h*HD);
    const float* vbase = V + ((size_t)(b*SEQ)*DM + h*HD);

    // stage Q tile 128x64 into Ps
    #pragma unroll
    for (int i = 0; i < 8; i++) {
        int idx = (tid + i*256)*4;
        int r = idx >> 6, c = idx & 63;
        *(float4*)&Ps[r*PSTRIDE + c] = *(const float4*)(qbase + (size_t)r*DM + c);
    }
    __syncthreads();

    uint32_t qh[8][4], ql[8][4];
    {
        int r = warp*16 + (lane >> 2);
        #pragma unroll
        for (int kc = 0; kc < 8; kc++) {
            int c = kc*8 + (lane & 3);
            split_tf32(Ps[r*PSTRIDE + c],         qh[kc][0], ql[kc][0]);
            split_tf32(Ps[(r+8)*PSTRIDE + c],     qh[kc][1], ql[kc][1]);
            split_tf32(Ps[r*PSTRIDE + c + 4],     qh[kc][2], ql[kc][2]);
            split_tf32(Ps[(r+8)*PSTRIDE + c + 4], qh[kc][3], ql[kc][3]);
        }
    }

    float o[8][4] = {};
    float mrow[2] = {-1e30f, -1e30f};
    float lrow[2] = {0.f, 0.f};

    for (int t = 0; t < SEQ/64; t++) {
        __syncthreads();
        #pragma unroll
        for (int i = 0; i < 4; i++) {   // K,V tiles 64x64, split at fill
            int idx = (tid + i*256)*4;
            int r = idx >> 6, c = idx & 63;
            float4 kv = *(const float4*)(kbase + (size_t)(t*64 + r)*DM + c);
            float4 vv = *(const float4*)(vbase + (size_t)(t*64 + r)*DM + c);
            float4 hh, ll;
            split4(kv, hh, ll);
            *(float4*)&Kh[r*KSTRIDE + c] = hh;
            *(float4*)&Kl[r*KSTRIDE + c] = ll;
            split4(vv, hh, ll);
            *(float4*)&Vh[r*KSTRIDE + c] = hh;
            *(float4*)&Vl[r*KSTRIDE + c] = ll;
        }
        __syncthreads();

        float s[8][4] = {};
        #pragma unroll
        for (int kc = 0; kc < 8; kc++) {
            #pragma unroll
            for (int ni = 0; ni < 8; ni++) {
                uint32_t bh[2], bl[2];
                int kr = ni*8 + (lane >> 2);
                int cc = kc*8 + (lane & 3);
                bh[0] = __float_as_uint(Kh[kr*KSTRIDE + cc]);
                bh[1] = __float_as_uint(Kh[kr*KSTRIDE + cc + 4]);
                bl[0] = __float_as_uint(Kl[kr*KSTRIDE + cc]);
                bl[1] = __float_as_uint(Kl[kr*KSTRIDE + cc + 4]);
                mma_tf32(s[ni], qh[kc], bh);
                mma_tf32(s[ni], ql[kc], bh);
                mma_tf32(s[ni], qh[kc], bl);
            }
        }
        #pragma unroll
        for (int ni = 0; ni < 8; ni++) {
            s[ni][0] *= 0.125f; s[ni][1] *= 0.125f;
            s[ni][2] *= 0.125f; s[ni][3] *= 0.125f;
        }

        // online softmax per row-half
        #pragma unroll
        for (int rh = 0; rh < 2; rh++) {
            float mx = -1e30f;
            #pragma unroll
            for (int ni = 0; ni < 8; ni++)
                mx = fmaxf(mx, fmaxf(s[ni][rh*2], s[ni][rh*2+1]));
            mx = fmaxf(mx, __shfl_xor_sync(0xffffffffu, mx, 1));
            mx = fmaxf(mx, __shfl_xor_sync(0xffffffffu, mx, 2));
            float mnew  = fmaxf(mrow[rh], mx);
            float alpha = __expf(mrow[rh] - mnew);
            mrow[rh] = mnew;
            float sum = 0.f;
            #pragma unroll
            for (int ni = 0; ni < 8; ni++) {
                s[ni][rh*2]   = __expf(s[ni][rh*2]   - mnew);
                s[ni][rh*2+1] = __expf(s[ni][rh*2+1] - mnew);
                sum += s[ni][rh*2] + s[ni][rh*2+1];
            }
            sum += __shfl_xor_sync(0xffffffffu, sum, 1);
            sum += __shfl_xor_sync(0xffffffffu, sum, 2);
            lrow[rh] = lrow[rh]*alpha + sum;
            #pragma unroll
            for (int ni = 0; ni < 8; ni++) { o[ni][rh*2] *= alpha; o[ni][rh*2+1] *= alpha; }
        }

        // P -> shared (per-warp rows, warp-private)
        {
            int r = warp*16 + (lane >> 2);
            #pragma unroll
            for (int ni = 0; ni < 8; ni++) {
                int c = ni*8 + 2*(lane & 3);
                Ps[r*PSTRIDE + c]         = s[ni][0];
                Ps[r*PSTRIDE + c + 1]     = s[ni][1];
                Ps[(r+8)*PSTRIDE + c]     = s[ni][2];
                Ps[(r+8)*PSTRIDE + c + 1] = s[ni][3];
            }
        }
        __syncwarp();

        // O += P @ V  (3xTF32), P split per-warp (no redundancy)
        #pragma unroll
        for (int kc = 0; kc < 8; kc++) {
            uint32_t ph[4], pl[4];
            int r = warp*16 + (lane >> 2);
            int c = kc*8 + (lane & 3);
            split_tf32(Ps[r*PSTRIDE + c],         ph[0], pl[0]);
            split_tf32(Ps[(r+8)*PSTRIDE + c],     ph[1], pl[1]);
            split_tf32(Ps[r*PSTRIDE + c + 4],     ph[2], pl[2]);
            split_tf32(Ps[(r+8)*PSTRIDE + c + 4], ph[3], pl[3]);
            #pragma unroll
            for (int ni = 0; ni < 8; ni++) {
                uint32_t vh[2], vl[2];
                int kr = kc*8 + (lane & 3);
                int cc = ni*8 + (lane >> 2);
                vh[0] = __float_as_uint(Vh[kr*KSTRIDE + cc]);
                vh[1] = __float_as_uint(Vh[(kr+4)*KSTRIDE + cc]);
                vl[0] = __float_as_uint(Vl[kr*KSTRIDE + cc]);
                vl[1] = __float_as_uint(Vl[(kr+4)*KSTRIDE + cc]);
                mma_tf32(o[ni], ph, vh);
                mma_tf32(o[ni], pl, vh);
                mma_tf32(o[ni], ph, vl);
            }
        }
        __syncwarp();
    }

    float inv0 = 1.f / lrow[0], inv1 = 1.f / lrow[1];
    int r = warp*16 + (lane >> 2);
    float* obase = O + ((size_t)(b*SEQ + qt*128)*DM + h*HD);
    #pragma unroll
    for (int ni = 0; ni < 8; ni++) {
        int c = ni*8 + 2*(lane & 3);
        obase[(size_t)r*DM + c]         = o[ni][0]*inv0;
        obase[(size_t)r*DM + c + 1]     = o[ni][1]*inv0;
        obase[(size_t)(r+8)*DM + c]     = o[ni][2]*inv1;
        obase[(size_t)(r+8)*DM + c + 1] = o[ni][3]*inv1;
    }
}

// ---------------- final LN ---------------------------------------------------
__global__ __launch_bounds__(256) void ln_out_kernel(
    const float* __restrict__ x, const float* __restrict__ gg,
    const float* __restrict__ bb, float* __restrict__ out)
{
    const int row = blockIdx.x;
    const int tid = threadIdx.x, lane = tid & 31, warp = tid >> 5;
    float4 xv = ((const float4*)(x + (size_t)row*DM))[tid];
    float s  = xv.x + xv.y + xv.z + xv.w;
    float ss = xv.x*xv.x + xv.y*xv.y + xv.z*xv.z + xv.w*xv.w;
    __shared__ __align__(16) float red[16];
    #pragma unroll
    for (int off = 16; off; off >>= 1) {
        s  += __shfl_xor_sync(0xffffffffu, s,  off);
        ss += __shfl_xor_sync(0xffffffffu, ss, off);
    }
    if (lane == 0) { red[warp] = s; red[8 + warp] = ss; }
    __syncthreads();
    float st = 0.f, sst = 0.f;
    #pragma unroll
    for (int i = 0; i < 8; i++) { st += red[i]; sst += red[8 + i]; }
    float mu   = st * (1.f/DM);
    float var  = sst * (1.f/DM) - mu*mu;
    float rstd = rsqrtf(var + EPS);
    float4 gv = ((const float4*)gg)[tid];
    float4 bv = ((const float4*)bb)[tid];
    float4 yv;
    yv.x = (xv.x - mu)*rstd*gv.x + bv.x;
    yv.y = (xv.y - mu)*rstd*gv.y + bv.y;
    yv.z = (xv.z - mu)*rstd*gv.z + bv.z;
    yv.w = (xv.w - mu)*rstd*gv.w + bv.w;
    ((float4*)(out + (size_t)row*DM))[tid] = yv;
}

// ---------------- launch -----------------------------------------------------
extern "C" void kernel_launch(void* const* d_in, const int* in_sizes, int n_in,
                              void* d_out, int out_size) {
    const float* query  = (const float*)d_in[0];
    const float* key_   = (const float*)d_in[1];
    const float* value  = (const float*)d_in[2];
    const float* Wq     = (const float*)d_in[3];
    const float* bq     = (const float*)d_in[4];
    const float* Wk     = (const float*)d_in[5];
    const float* bk     = (const float*)d_in[6];
    const float* Wv     = (const float*)d_in[7];
    const float* bv     = (const float*)d_in[8];
    const float* Wo     = (const float*)d_in[9];
    const float* bo     = (const float*)d_in[10];
    const float* Wg     = (const float*)d_in[11];
    const float* ln_q_g = (const float*)d_in[12];
    const float* ln_q_b = (const float*)d_in[13];
    const float* ln_kv_g= (const float*)d_in[14];
    const float* ln_kv_b= (const float*)d_in[15];
    const float* ln_o_g = (const float*)d_in[16];
    const float* ln_o_b = (const float*)d_in[17];

    float *qn, *kn, *vn, *qp, *kp, *vp, *ao, *y, *gate;
    cudaGetSymbolAddress((void**)&qn,  g_qn);
    cudaGetSymbolAddress((void**)&kn,  g_kn);
    cudaGetSymbolAddress((void**)&vn,  g_vn);
    cudaGetSymbolAddress((void**)&qp,  g_qp);
    cudaGetSymbolAddress((void**)&kp,  g_kp);
    cudaGetSymbolAddress((void**)&vp,  g_vp);
    cudaGetSymbolAddress((void**)&ao,  g_ao);
    cudaGetSymbolAddress((void**)&y,   g_y);
    cudaGetSymbolAddress((void**)&gate,g_gate);

    const int gemm_smem = (2*128*ASTRIDE + 2*32*BSTRIDE) * (int)sizeof(float);
    const int attn_smem = (4*64*KSTRIDE + 128*PSTRIDE) * (int)sizeof(float);
    static bool attr_set = false;
    if (!attr_set) {
        cudaFuncSetAttribute(gemm_tf32, cudaFuncAttributeMaxDynamicSharedMemorySize, gemm_smem);
        cudaFuncSetAttribute(attn_kernel, cudaFuncAttributeMaxDynamicSharedMemorySize, attn_smem);
        attr_set = true;
    }

    ln3_kernel<<<dim3(MTOT, 3), 256>>>(query, key_, value,
                                       ln_q_g, ln_q_b, ln_kv_g, ln_kv_b,
                                       Wg, qn, kn, vn, gate);
    gemm_tf32<<<dim3(8, 64), 256, gemm_smem>>>(qn, Wq, bq, nullptr, qp);
    gemm_tf32<<<dim3(8, 64), 256, gemm_smem>>>(kn, Wk, bk, nullptr, kp);
    gemm_tf32<<<dim3(8, 64), 256, gemm_smem>>>(vn, Wv, bv, nullptr, vp);
    attn_kernel<<<dim3(SEQ/128, NH, BATCH), 256, attn_smem>>>(qp, kp, vp, ao);
    gemm_tf32<<<dim3(8, 64), 256, gemm_smem>>>(ao, Wo, bo, gate, y);
    ln_out_kernel<<<MTOT, 256>>>(y, ln_o_g, ln_o_b, (float*)d_out);
}

// round 5
// speedup vs baseline: 2.4877x; 2.2915x over previous
#include <cuda_runtime.h>
#include <cuda_bf16.h>
#include <cstdint>

#define DM   1024
#define BATCH 4
#define SEQ  2048
#define NH   16
#define HD   64
#define MTOT (BATCH*SEQ)   /* 8192 */
#define EPS  1e-5f

// ---------------- scratch (device globals; no allocations allowed) ----------
__device__ float g_qn[MTOT*DM];
__device__ float g_kn[MTOT*DM];
__device__ float g_vn[MTOT*DM];
__device__ float g_qp[MTOT*DM];
__device__ float g_kp[MTOT*DM];
__device__ float g_vp[MTOT*DM];
__device__ float g_ao[MTOT*DM];
__device__ float g_y [MTOT*DM];
__device__ float g_gate[MTOT];

// ---------------- bf16 mma m16n8k16 + ldmatrix helpers ----------------------
__device__ __forceinline__ void mma_bf16(float c[4], const uint32_t a[4], const uint32_t b[2]) {
    asm volatile(
        "mma.sync.aligned.m16n8k16.row.col.f32.bf16.bf16.f32 "
        "{%0,%1,%2,%3}, {%4,%5,%6,%7}, {%8,%9}, {%0,%1,%2,%3};\n"
        : "+f"(c[0]), "+f"(c[1]), "+f"(c[2]), "+f"(c[3])
        : "r"(a[0]), "r"(a[1]), "r"(a[2]), "r"(a[3]), "r"(b[0]), "r"(b[1]));
}

__device__ __forceinline__ uint32_t smem_u32(const void* p) {
    return (uint32_t)__cvta_generic_to_shared(p);
}

__device__ __forceinline__ void ldmx4(uint32_t r[4], uint32_t addr) {
    asm volatile("ldmatrix.sync.aligned.m8n8.x4.shared.b16 {%0,%1,%2,%3}, [%4];"
                 : "=r"(r[0]), "=r"(r[1]), "=r"(r[2]), "=r"(r[3]) : "r"(addr));
}
__device__ __forceinline__ void ldmx4t(uint32_t r[4], uint32_t addr) {
    asm volatile("ldmatrix.sync.aligned.m8n8.x4.trans.shared.b16 {%0,%1,%2,%3}, [%4];"
                 : "=r"(r[0]), "=r"(r[1]), "=r"(r[2]), "=r"(r[3]) : "r"(addr));
}

// pack two floats as bf16x2 (e0 -> low half, e1 -> high half), rn rounding
__device__ __forceinline__ uint32_t packb(float e0, float e1) {
    uint32_t r;
    asm("cvt.rn.bf16x2.f32 %0, %1, %2;" : "=r"(r) : "f"(e1), "f"(e0));
    return r;
}
__device__ __forceinline__ float hi_bf16(float x) {
    return __bfloat162float(__float2bfloat16(x));
}
// split float4 into hi/lo bf16x2 pairs (elementwise x = hi + lo, both bf16)
__device__ __forceinline__ void split4b(float4 v, uint2& h, uint2& l) {
    float hx = hi_bf16(v.x), hy = hi_bf16(v.y), hz = hi_bf16(v.z), hw = hi_bf16(v.w);
    h.x = packb(hx, hy); h.y = packb(hz, hw);
    l.x = packb(v.x - hx, v.y - hy); l.y = packb(v.z - hz, v.w - hw);
}

// ---------------- fused pre-LN for q/k/v + gate ------------------------------
__global__ __launch_bounds__(256) void ln3_kernel(
    const float* __restrict__ q, const float* __restrict__ k, const float* __restrict__ v,
    const float* __restrict__ gq, const float* __restrict__ bq,
    const float* __restrict__ gkv, const float* __restrict__ bkv,
    const float* __restrict__ Wg,
    float* __restrict__ oq, float* __restrict__ ok, float* __restrict__ ov,
    float* __restrict__ gate)
{
    const int row = blockIdx.x, src = blockIdx.y;
    const float* x  = src == 0 ? q  : (src == 1 ? k  : v);
    float*       out= src == 0 ? oq : (src == 1 ? ok : ov);
    const float* gg = src == 0 ? gq : gkv;
    const float* bb = src == 0 ? bq : bkv;
    const int tid = threadIdx.x, lane = tid & 31, warp = tid >> 5;

    float4 xv = ((const float4*)(x + (size_t)row*DM))[tid];
    float s  = xv.x + xv.y + xv.z + xv.w;
    float ss = xv.x*xv.x + xv.y*xv.y + xv.z*xv.z + xv.w*xv.w;

    __shared__ __align__(16) float red[16];
    #pragma unroll
    for (int off = 16; off; off >>= 1) {
        s  += __shfl_xor_sync(0xffffffffu, s,  off);
        ss += __shfl_xor_sync(0xffffffffu, ss, off);
    }
    if (lane == 0) { red[warp] = s; red[8 + warp] = ss; }
    __syncthreads();
    float st = 0.f, sst = 0.f;
    #pragma unroll
    for (int i = 0; i < 8; i++) { st += red[i]; sst += red[8 + i]; }
    float mu   = st * (1.f/DM);
    float var  = sst * (1.f/DM) - mu*mu;
    float rstd = rsqrtf(var + EPS);

    float4 gv = ((const float4*)gg)[tid];
    float4 bv = ((const float4*)bb)[tid];
    float4 yv;
    yv.x = (xv.x - mu)*rstd*gv.x + bv.x;
    yv.y = (xv.y - mu)*rstd*gv.y + bv.y;
    yv.z = (xv.z - mu)*rstd*gv.z + bv.z;
    yv.w = (xv.w - mu)*rstd*gv.w + bv.w;
    ((float4*)(out + (size_t)row*DM))[tid] = yv;

    if (src == 0) {  // gate = sigmoid(qn . Wg)
        float4 wv = ((const float4*)Wg)[tid];
        float gp = yv.x*wv.x + yv.y*wv.y + yv.z*wv.z + yv.w*wv.w;
        #pragma unroll
        for (int off = 16; off; off >>= 1) gp += __shfl_xor_sync(0xffffffffu, gp, off);
        __syncthreads();
        if (lane == 0) red[warp] = gp;
        __syncthreads();
        if (tid == 0) {
            float t = 0.f;
            #pragma unroll
            for (int i = 0; i < 8; i++) t += red[i];
            gate[row] = 1.f / (1.f + __expf(-t));
        }
    }
}

// ---------------- 3xBF16 GEMM: C[M,N] = A[M,K] @ W[K,N] + bias (xgate) ------
// BM=128, BN=64, BK=32. 256 threads, 8 warps (4m x 2n), warp tile 32x32.
#define AST 40   /* bf16 elems per A smem row (32 + 8 pad), 80B stride */
#define BST 72   /* bf16 elems per B smem row (64 + 8 pad), 144B stride */
__global__ __launch_bounds__(256, 2) void gemm_bf16x3(
    const float* __restrict__ A, const float* __restrict__ W,
    const float* __restrict__ bias, const float* __restrict__ gate,
    float* __restrict__ C)
{
    __shared__ __align__(16) __nv_bfloat16 Ah[128*AST], Al[128*AST];
    __shared__ __align__(16) __nv_bfloat16 Bh[32*BST],  Bl[32*BST];

    const int tid = threadIdx.x, lane = tid & 31, warp = tid >> 5;
    const int bm = blockIdx.y * 128, bn = blockIdx.x * 64;
    const int wm = (warp >> 1) * 32, wn = (warp & 1) * 32;

    float acc[2][4][4] = {};
    float4 pa[4], pb[2];

    auto loadT = [&](int k0) {
        #pragma unroll
        for (int i = 0; i < 4; i++) {
            int idx = (tid + i*256) * 4;
            int m = idx >> 5, kk = idx & 31;
            pa[i] = *(const float4*)(A + (size_t)(bm + m)*1024 + k0 + kk);
        }
        #pragma unroll
        for (int i = 0; i < 2; i++) {
            int idx = (tid + i*256) * 4;
            int kk = idx >> 6, n = idx & 63;
            pb[i] = *(const float4*)(W + (size_t)(k0 + kk)*1024 + bn + n);
        }
    };
    auto storeT = [&]() {
        #pragma unroll
        for (int i = 0; i < 4; i++) {
            int idx = (tid + i*256) * 4;
            int m = idx >> 5, kk = idx & 31;
            uint2 h, l; split4b(pa[i], h, l);
            *(uint2*)&Ah[m*AST + kk] = h;
            *(uint2*)&Al[m*AST + kk] = l;
        }
        #pragma unroll
        for (int i = 0; i < 2; i++) {
            int idx = (tid + i*256) * 4;
            int kk = idx >> 6, n = idx & 63;
            uint2 h, l; split4b(pb[i], h, l);
            *(uint2*)&Bh[kk*BST + n] = h;
            *(uint2*)&Bl[kk*BST + n] = l;
        }
    };

    loadT(0); storeT(); __syncthreads();

    const uint32_t ah_b = smem_u32(Ah), al_b = smem_u32(Al);
    const uint32_t bh_b = smem_u32(Bh), bl_b = smem_u32(Bl);

    for (int k0 = 0; k0 < 1024; k0 += 32) {
        bool more = (k0 + 32 < 1024);
        if (more) loadT(k0 + 32);

        #pragma unroll
        for (int kc = 0; kc < 2; kc++) {
            uint32_t af_h[2][4], af_l[2][4];
            #pragma unroll
            for (int mi = 0; mi < 2; mi++) {
                uint32_t off = ((wm + mi*16 + (lane & 15))*AST + kc*16 + (lane >> 4)*8) * 2;
                ldmx4(af_h[mi], ah_b + off);
                ldmx4(af_l[mi], al_b + off);
            }
            uint32_t bf_h[2][4], bf_l[2][4];
            #pragma unroll
            for (int nip = 0; nip < 2; nip++) {
                uint32_t off = ((kc*16 + (lane & 15))*BST + wn + nip*16 + (lane >> 4)*8) * 2;
                ldmx4t(bf_h[nip], bh_b + off);
                ldmx4t(bf_l[nip], bl_b + off);
            }
            #pragma unroll
            for (int mi = 0; mi < 2; mi++)
                #pragma unroll
                for (int ni = 0; ni < 4; ni++) {
                    const uint32_t* b2h = &bf_h[ni >> 1][(ni & 1)*2];
                    const uint32_t* b2l = &bf_l[ni >> 1][(ni & 1)*2];
                    mma_bf16(acc[mi][ni], af_h[mi], b2h);
                    mma_bf16(acc[mi][ni], af_l[mi], b2h);
                    mma_bf16(acc[mi][ni], af_h[mi], b2l);
                }
        }

        if (more) {
            __syncthreads();
            storeT();
            __syncthreads();
        }
    }

    #pragma unroll
    for (int mi = 0; mi < 2; mi++) {
        #pragma unroll
        for (int ni = 0; ni < 4; ni++) {
            int r0 = bm + wm + mi*16 + (lane >> 2);
            int c0 = bn + wn + ni*8 + 2*(lane & 3);
            float bz0 = bias[c0], bz1 = bias[c0 + 1];
            float v0 = acc[mi][ni][0] + bz0;
            float v1 = acc[mi][ni][1] + bz1;
            float v2 = acc[mi][ni][2] + bz0;
            float v3 = acc[mi][ni][3] + bz1;
            if (gate) {
                float gA = gate[r0], gB = gate[r0 + 8];
                v0 *= gA; v1 *= gA; v2 *= gB; v3 *= gB;
            }
            C[(size_t)r0*1024 + c0]         = v0;
            C[(size_t)r0*1024 + c0 + 1]     = v1;
            C[(size_t)(r0+8)*1024 + c0]     = v2;
            C[(size_t)(r0+8)*1024 + c0 + 1] = v3;
        }
    }
}

// ---------------- flash attention (3xBF16 mma, online softmax) ---------------
// grid (SEQ/128, NH, BATCH), 256 threads (8 warps x 16 q-rows). Hd=64.
// P stays in registers (acc layout == A-fragment layout). K/V bf16 hi/lo tiles.
#define KST 72   /* bf16 elems per row (64 + 8 pad), 144B stride */
__global__ __launch_bounds__(256, 1) void attn_bf16(
    const float* __restrict__ Q, const float* __restrict__ K,
    const float* __restrict__ V, float* __restrict__ O)
{
    __shared__ __align__(16) __nv_bfloat16 smem[4*64*KST];  /* 36,864 B */
    __nv_bfloat16* Qh = smem;                 // 128*KST (aliases Kh+Kl)
    __nv_bfloat16* Ql = smem + 2*64*KST;      // 128*KST (aliases Vh+Vl)
    __nv_bfloat16* Kh = smem;
    __nv_bfloat16* Kl = smem + 64*KST;
    __nv_bfloat16* Vh = smem + 2*64*KST;
    __nv_bfloat16* Vl = smem + 3*64*KST;

    const int tid = threadIdx.x, lane = tid & 31, warp = tid >> 5;
    const int qt = blockIdx.x, h = blockIdx.y, b = blockIdx.z;

    const float* qbase = Q + ((size_t)(b*SEQ + qt*128)*DM + h*HD);
    const float* kbase = K + ((size_t)(b*SEQ)*DM + h*HD);
    const float* vbase = V + ((size_t)(b*SEQ)*DM + h*HD);

    // stage Q tile 128x64, split hi/lo
    #pragma unroll
    for (int i = 0; i < 8; i++) {
        int idx = (tid + i*256)*4;
        int r = idx >> 6, c = idx & 63;
        float4 v = *(const float4*)(qbase + (size_t)r*DM + c);
        uint2 hh, ll; split4b(v, hh, ll);
        *(uint2*)&Qh[r*KST + c] = hh;
        *(uint2*)&Ql[r*KST + c] = ll;
    }
    __syncthreads();

    uint32_t qh[4][4], ql[4][4];
    {
        const uint32_t qh_b = smem_u32(Qh), ql_b = smem_u32(Ql);
        #pragma unroll
        for (int kc = 0; kc < 4; kc++) {
            uint32_t off = ((warp*16 + (lane & 15))*KST + kc*16 + (lane >> 4)*8) * 2;
            ldmx4(qh[kc], qh_b + off);
            ldmx4(ql[kc], ql_b + off);
        }
    }

    const uint32_t kh_b = smem_u32(Kh), kl_b = smem_u32(Kl);
    const uint32_t vh_b = smem_u32(Vh), vl_b = smem_u32(Vl);

    float o[8][4] = {};
    float mrow[2] = {-1e30f, -1e30f};
    float lrow[2] = {0.f, 0.f};

    float4 pk[4], pv[4];
    auto loadKV = [&](int t) {
        #pragma unroll
        for (int i = 0; i < 4; i++) {
            int idx = (tid + i*256)*4;
            int r = idx >> 6, c = idx & 63;
            pk[i] = *(const float4*)(kbase + (size_t)(t*64 + r)*DM + c);
            pv[i] = *(const float4*)(vbase + (size_t)(t*64 + r)*DM + c);
        }
    };
    auto storeKV = [&]() {
        #pragma unroll
        for (int i = 0; i < 4; i++) {
            int idx = (tid + i*256)*4;
            int r = idx >> 6, c = idx & 63;
            uint2 hh, ll;
            split4b(pk[i], hh, ll);
            *(uint2*)&Kh[r*KST + c] = hh;
            *(uint2*)&Kl[r*KST + c] = ll;
            split4b(pv[i], hh, ll);
            *(uint2*)&Vh[r*KST + c] = hh;
            *(uint2*)&Vl[r*KST + c] = ll;
        }
    };

    loadKV(0);

    for (int t = 0; t < SEQ/64; t++) {
        __syncthreads();
        storeKV();
        __syncthreads();
        if (t + 1 < SEQ/64) loadKV(t + 1);

        // ---- S = Q K^T (3xBF16) ----
        float s[8][4] = {};
        #pragma unroll
        for (int kc = 0; kc < 4; kc++) {
            #pragma unroll
            for (int nip = 0; nip < 4; nip++) {
                // non-trans x4 on K[n][d]: r0,r1 = frag(ni), r2,r3 = frag(ni+1)
                uint32_t off = ((nip*16 + (lane >> 4)*8 + (lane & 7))*KST
                                + kc*16 + ((lane >> 3) & 1)*8) * 2;
                uint32_t kf_h[4], kf_l[4];
                ldmx4(kf_h, kh_b + off);
                ldmx4(kf_l, kl_b + off);
                #pragma unroll
                for (int hf = 0; hf < 2; hf++) {
                    int ni = nip*2 + hf;
                    mma_bf16(s[ni], qh[kc], &kf_h[hf*2]);
                    mma_bf16(s[ni], ql[kc], &kf_h[hf*2]);
                    mma_bf16(s[ni], qh[kc], &kf_l[hf*2]);
                }
            }
        }
        #pragma unroll
        for (int ni = 0; ni < 8; ni++) {
            s[ni][0] *= 0.125f; s[ni][1] *= 0.125f;
            s[ni][2] *= 0.125f; s[ni][3] *= 0.125f;
        }

        // ---- online softmax per row-half ----
        #pragma unroll
        for (int rh = 0; rh < 2; rh++) {
            float mx = -1e30f;
            #pragma unroll
            for (int ni = 0; ni < 8; ni++)
                mx = fmaxf(mx, fmaxf(s[ni][rh*2], s[ni][rh*2+1]));
            mx = fmaxf(mx, __shfl_xor_sync(0xffffffffu, mx, 1));
            mx = fmaxf(mx, __shfl_xor_sync(0xffffffffu, mx, 2));
            float mnew  = fmaxf(mrow[rh], mx);
            float alpha = __expf(mrow[rh] - mnew);
            mrow[rh] = mnew;
            float sum = 0.f;
            #pragma unroll
            for (int ni = 0; ni < 8; ni++) {
                s[ni][rh*2]   = __expf(s[ni][rh*2]   - mnew);
                s[ni][rh*2+1] = __expf(s[ni][rh*2+1] - mnew);
                sum += s[ni][rh*2] + s[ni][rh*2+1];
            }
            sum += __shfl_xor_sync(0xffffffffu, sum, 1);
            sum += __shfl_xor_sync(0xffffffffu, sum, 2);
            lrow[rh] = lrow[rh]*alpha + sum;
            #pragma unroll
            for (int ni = 0; ni < 8; ni++) { o[ni][rh*2] *= alpha; o[ni][rh*2+1] *= alpha; }
        }

        // ---- O += P V (3xBF16); P fragments built directly from s regs ----
        #pragma unroll
        for (int kcp = 0; kcp < 4; kcp++) {
            // A-frag (m16 k16): a0=(s[2kcp]c0,c1) a1=(c2,c3) a2=(s[2kcp+1]c0,c1) a3=(c2,c3)
            uint32_t ph[4], pl[4];
            #pragma unroll
            for (int j = 0; j < 2; j++) {
                float e0 = s[2*kcp + j][0], e1 = s[2*kcp + j][1];
                float e2 = s[2*kcp + j][2], e3 = s[2*kcp + j][3];
                float h0 = hi_bf16(e0), h1 = hi_bf16(e1), h2 = hi_bf16(e2), h3 = hi_bf16(e3);
                ph[2*j]   = packb(h0, h1);
                ph[2*j+1] = packb(h2, h3);
                pl[2*j]   = packb(e0 - h0, e1 - h1);
                pl[2*j+1] = packb(e2 - h2, e3 - h3);
            }
            // fix ordering: frag is {a0,a1,a2,a3} = {blk(m0-7,k0-7), blk(m8-15,k0-7), ...}
            uint32_t pa_h[4] = { ph[0], ph[1], ph[2], ph[3] };
            uint32_t pa_l[4] = { pl[0], pl[1], pl[2], pl[3] };

            #pragma unroll
            for (int nip = 0; nip < 4; nip++) {
                // trans x4 on V[k][d]: r0,r1 = frag(d-block ni), r2,r3 = frag(ni+1)
                uint32_t off = ((kcp*16 + ((lane >> 3) & 1)*8 + (lane & 7))*KST
                                + nip*16 + (lane >> 4)*8) * 2;
                uint32_t vf_h[4], vf_l[4];
                ldmx4t(vf_h, vh_b + off);
                ldmx4t(vf_l, vl_b + off);
                #pragma unroll
                for (int hf = 0; hf < 2; hf++) {
                    int ni = nip*2 + hf;
                    mma_bf16(o[ni], pa_h, &vf_h[hf*2]);
                    mma_bf16(o[ni], pa_l, &vf_h[hf*2]);
                    mma_bf16(o[ni], pa_h, &vf_l[hf*2]);
                }
            }
        }
    }

    float inv0 = 1.f / lrow[0], inv1 = 1.f / lrow[1];
    int r = warp*16 + (lane >> 2);
    float* obase = O + ((size_t)(b*SEQ + qt*128)*DM + h*HD);
    #pragma unroll
    for (int ni = 0; ni < 8; ni++) {
        int c = ni*8 + 2*(lane & 3);
        obase[(size_t)r*DM + c]         = o[ni][0]*inv0;
        obase[(size_t)r*DM + c + 1]     = o[ni][1]*inv0;
        obase[(size_t)(r+8)*DM + c]     = o[ni][2]*inv1;
        obase[(size_t)(r+8)*DM + c + 1] = o[ni][3]*inv1;
    }
}

// ---------------- final LN ---------------------------------------------------
__global__ __launch_bounds__(256) void ln_out_kernel(
    const float* __restrict__ x, const float* __restrict__ gg,
    const float* __restrict__ bb, float* __restrict__ out)
{
    const int row = blockIdx.x;
    const int tid = threadIdx.x, lane = tid & 31, warp = tid >> 5;
    float4 xv = ((const float4*)(x + (size_t)row*DM))[tid];
    float s  = xv.x + xv.y + xv.z + xv.w;
    float ss = xv.x*xv.x + xv.y*xv.y + xv.z*xv.z + xv.w*xv.w;
    __shared__ __align__(16) float red[16];
    #pragma unroll
    for (int off = 16; off; off >>= 1) {
        s  += __shfl_xor_sync(0xffffffffu, s,  off);
        ss += __shfl_xor_sync(0xffffffffu, ss, off);
    }
    if (lane == 0) { red[warp] = s; red[8 + warp] = ss; }
    __syncthreads();
    float st = 0.f, sst = 0.f;
    #pragma unroll
    for (int i = 0; i < 8; i++) { st += red[i]; sst += red[8 + i]; }
    float mu   = st * (1.f/DM);
    float var  = sst * (1.f/DM) - mu*mu;
    float rstd = rsqrtf(var + EPS);
    float4 gv = ((const float4*)gg)[tid];
    float4 bv = ((const float4*)bb)[tid];
    float4 yv;
    yv.x = (xv.x - mu)*rstd*gv.x + bv.x;
    yv.y = (xv.y - mu)*rstd*gv.y + bv.y;
    yv.z = (xv.z - mu)*rstd*gv.z + bv.z;
    yv.w = (xv.w - mu)*rstd*gv.w + bv.w;
    ((float4*)(out + (size_t)row*DM))[tid] = yv;
}

// ---------------- launch -----------------------------------------------------
extern "C" void kernel_launch(void* const* d_in, const int* in_sizes, int n_in,
                              void* d_out, int out_size) {
    const float* query  = (const float*)d_in[0];
    const float* key_   = (const float*)d_in[1];
    const float* value  = (const float*)d_in[2];
    const float* Wq     = (const float*)d_in[3];
    const float* bq     = (const float*)d_in[4];
    const float* Wk     = (const float*)d_in[5];
    const float* bk     = (const float*)d_in[6];
    const float* Wv     = (const float*)d_in[7];
    const float* bv     = (const float*)d_in[8];
    const float* Wo     = (const float*)d_in[9];
    const float* bo     = (const float*)d_in[10];
    const float* Wg     = (const float*)d_in[11];
    const float* ln_q_g = (const float*)d_in[12];
    const float* ln_q_b = (const float*)d_in[13];
    const float* ln_kv_g= (const float*)d_in[14];
    const float* ln_kv_b= (const float*)d_in[15];
    const float* ln_o_g = (const float*)d_in[16];
    const float* ln_o_b = (const float*)d_in[17];

    float *qn, *kn, *vn, *qp, *kp, *vp, *ao, *y, *gate;
    cudaGetSymbolAddress((void**)&qn,  g_qn);
    cudaGetSymbolAddress((void**)&kn,  g_kn);
    cudaGetSymbolAddress((void**)&vn,  g_vn);
    cudaGetSymbolAddress((void**)&qp,  g_qp);
    cudaGetSymbolAddress((void**)&kp,  g_kp);
    cudaGetSymbolAddress((void**)&vp,  g_vp);
    cudaGetSymbolAddress((void**)&ao,  g_ao);
    cudaGetSymbolAddress((void**)&y,   g_y);
    cudaGetSymbolAddress((void**)&gate,g_gate);

    ln3_kernel<<<dim3(MTOT, 3), 256>>>(query, key_, value,
                                       ln_q_g, ln_q_b, ln_kv_g, ln_kv_b,
                                       Wg, qn, kn, vn, gate);
    gemm_bf16x3<<<dim3(16, 64), 256>>>(qn, Wq, bq, nullptr, qp);
    gemm_bf16x3<<<dim3(16, 64), 256>>>(kn, Wk, bk, nullptr, kp);
    gemm_bf16x3<<<dim3(16, 64), 256>>>(vn, Wv, bv, nullptr, vp);
    attn_bf16<<<dim3(SEQ/128, NH, BATCH), 256>>>(qp, kp, vp, ao);
    gemm_bf16x3<<<dim3(16, 64), 256>>>(ao, Wo, bo, gate, y);
    ln_out_kernel<<<MTOT, 256>>>(y, ln_o_g, ln_o_b, (float*)d_out);
}